// round 4
// baseline (speedup 1.0000x reference)
#include <cuda_runtime.h>
#include <cstdint>

// SNN Leaky forward:  mem = 0.5*mem + x_t - spk;  spk = (mem > 1) ? 1 : 0
// x: [128, 64*4096] f32 -> spk same shape.
//
// R4: loads moved off the LDG/L1tex path onto the TMA bulk-copy engine.
// 16-stage mbarrier ring of 2KB cp.async.bulk loads per CTA (32KB in
// flight/CTA), compute from SMEM, direct STG.128 streaming stores.
// Hypothesis: per-SM LDG in-flight cap was binding DRAM at ~68%.

#define T_STEPS 128
#define TOTAL_COLS 262144                    // floats per timestep (1MiB)
#define COLS_PER_CTA 512                     // floats (2KB) per CTA slice
#define NCTA (TOTAL_COLS / COLS_PER_CTA)     // 512 CTAs
#define STAGES 16
#define STAGE_BYTES (COLS_PER_CTA * 4)       // 2048

__device__ __forceinline__ uint32_t s2u(const void* p) {
    return (uint32_t)__cvta_generic_to_shared(p);
}
__device__ __forceinline__ void mbar_init(uint32_t a, uint32_t cnt) {
    asm volatile("mbarrier.init.shared::cta.b64 [%0], %1;" :: "r"(a), "r"(cnt) : "memory");
}
__device__ __forceinline__ void mbar_arrive(uint32_t a) {
    asm volatile("mbarrier.arrive.shared::cta.b64 _, [%0];" :: "r"(a) : "memory");
}
__device__ __forceinline__ void mbar_expect_tx(uint32_t a, uint32_t bytes) {
    asm volatile("mbarrier.arrive.expect_tx.shared::cta.b64 _, [%0], %1;"
                 :: "r"(a), "r"(bytes) : "memory");
}
__device__ __forceinline__ void mbar_wait(uint32_t a, uint32_t parity) {
    asm volatile(
        "{\n\t.reg .pred P;\n\t"
        "LW_%=:\n\t"
        "mbarrier.try_wait.parity.acquire.cta.shared::cta.b64 P, [%0], %1, 0x989680;\n\t"
        "@P bra LD_%=;\n\t"
        "bra LW_%=;\n\t"
        "LD_%=:\n\t}"
        :: "r"(a), "r"(parity) : "memory");
}
__device__ __forceinline__ void bulk_ld(uint32_t dst, const float* src,
                                        uint32_t bytes, uint32_t mbar) {
    asm volatile(
        "cp.async.bulk.shared::cta.global.mbarrier::complete_tx::bytes [%0], [%1], %2, [%3];"
        :: "r"(dst), "l"(src), "r"(bytes), "r"(mbar) : "memory");
}

__global__ __launch_bounds__(128) void snn_leaky_tma_kernel(
    const float* __restrict__ x, float* __restrict__ out)
{
    __shared__ alignas(1024) float buf[STAGES][COLS_PER_CTA];
    __shared__ alignas(8) uint64_t mb_full[STAGES];
    __shared__ alignas(8) uint64_t mb_empty[STAGES];

    const int tid = threadIdx.x;
    const int cta = blockIdx.x;
    const float* xbase = x + (size_t)cta * COLS_PER_CTA;
    float* obase = out + (size_t)cta * COLS_PER_CTA + tid * 4;

    if (tid == 0) {
        for (int s = 0; s < STAGES; s++) {
            mbar_init(s2u(&mb_full[s]), 1);
            mbar_init(s2u(&mb_empty[s]), 128);
        }
        asm volatile("fence.proxy.async.shared::cta;" ::: "memory");
    }
    __syncthreads();

    // prologue: fill all 16 stages (t = 0..15)
    if (tid == 0) {
        for (int s = 0; s < STAGES; s++) {
            mbar_expect_tx(s2u(&mb_full[s]), STAGE_BYTES);
            bulk_ld(s2u(&buf[s][0]), xbase + (size_t)s * TOTAL_COLS,
                    STAGE_BYTES, s2u(&mb_full[s]));
        }
    }

    float4 mem = make_float4(0.f, 0.f, 0.f, 0.f);
    float4 spk = make_float4(0.f, 0.f, 0.f, 0.f);

    for (int t = 0; t < T_STEPS; t++) {
        const int s = t & (STAGES - 1);
        const uint32_t ph = (t >> 4) & 1;

        mbar_wait(s2u(&mb_full[s]), ph);
        float4 xt = *(const float4*)&buf[s][tid * 4];

        mem.x = 0.5f * mem.x + xt.x - spk.x;
        mem.y = 0.5f * mem.y + xt.y - spk.y;
        mem.z = 0.5f * mem.z + xt.z - spk.z;
        mem.w = 0.5f * mem.w + xt.w - spk.w;

        spk.x = (mem.x > 1.0f) ? 1.0f : 0.0f;
        spk.y = (mem.y > 1.0f) ? 1.0f : 0.0f;
        spk.z = (mem.z > 1.0f) ? 1.0f : 0.0f;
        spk.w = (mem.w > 1.0f) ? 1.0f : 0.0f;

        __stcs((float4*)(obase + (size_t)t * TOTAL_COLS), spk);

        mbar_arrive(s2u(&mb_empty[s]));

        if (tid == 0 && t + STAGES < T_STEPS) {
            // reuse stage s for timestep t+16 once all 128 consumers arrived
            mbar_wait(s2u(&mb_empty[s]), ph);
            mbar_expect_tx(s2u(&mb_full[s]), STAGE_BYTES);
            bulk_ld(s2u(&buf[s][0]), xbase + (size_t)(t + STAGES) * TOTAL_COLS,
                    STAGE_BYTES, s2u(&mb_full[s]));
        }
    }
}

extern "C" void kernel_launch(void* const* d_in, const int* in_sizes, int n_in,
                              void* d_out, int out_size)
{
    const float* x = (const float*)d_in[0];
    float* o = (float*)d_out;
    snn_leaky_tma_kernel<<<NCTA, 128>>>(x, o);
}

// round 5
// speedup vs baseline: 1.2495x; 1.2495x over previous
#include <cuda_runtime.h>
#include <cstdint>

// SNN Leaky forward:  mem = 0.5*mem + x_t - spk;  spk = (mem > 1) ? 1 : 0
// x: [128, 64*4096] f32 -> spk same shape. Pure HBM streaming.
//
// R5 = R2 structure (best: 40.35us kernel) + L2 bulk prefetch:
//  - float4/thread, unroll-8 front-batched LDG.128, __ldcs/__stcs
//  - block=64, grid=1024 (max/avg CTA imbalance only 1.2%)
//  - tid0 issues cp.async.bulk.prefetch.L2 16 timesteps ahead so the
//    consumer LDGs hit L2 (~250cyc) instead of riding DRAM latency.
//    16KB/CTA x 1024 CTAs = 16MB resident, no L2 self-eviction.

#define T_STEPS 128
#define BN4 65536                 // (64*4096)/4 float4 columns per timestep
#define BLOCK 64
#define PF_DIST 16                // timesteps of prefetch lead
#define PF_BYTES (BLOCK * 16)     // 1KB slab per CTA per timestep

__device__ __forceinline__ void l2_prefetch(const void* p, uint32_t bytes) {
    asm volatile("cp.async.bulk.prefetch.L2.global [%0], %1;"
                 :: "l"(p), "r"(bytes) : "memory");
}

__global__ __launch_bounds__(BLOCK) void snn_leaky_kernel(
    const float4* __restrict__ x4, float4* __restrict__ o4)
{
    const int idx = blockIdx.x * BLOCK + threadIdx.x;   // 0..BN4-1
    const float4* xp = x4 + idx;
    float4* op = o4 + idx;

    // CTA's contiguous 1KB slab base for prefetching
    const float4* pf_base = x4 + blockIdx.x * BLOCK;

    // prologue: prefetch timesteps 0..PF_DIST-1
    if (threadIdx.x == 0) {
#pragma unroll
        for (int t = 0; t < PF_DIST; t++)
            l2_prefetch(pf_base + (size_t)t * BN4, PF_BYTES);
    }

    float4 mem = make_float4(0.f, 0.f, 0.f, 0.f);
    float4 spk = make_float4(0.f, 0.f, 0.f, 0.f);

    for (int t = 0; t < T_STEPS; t += 8) {
        // prefetch the batch PF_DIST ahead (1 thread, fire-and-forget)
        if (threadIdx.x == 0 && t + PF_DIST < T_STEPS) {
#pragma unroll
            for (int u = 0; u < 8; u++)
                l2_prefetch(pf_base + (size_t)(t + PF_DIST + u) * BN4, PF_BYTES);
        }

        // front-batch 8 independent loads (should mostly hit L2)
        float4 a[8];
#pragma unroll
        for (int u = 0; u < 8; u++)
            a[u] = __ldcs(xp + (size_t)(t + u) * BN4);

#pragma unroll
        for (int u = 0; u < 8; u++) {
            mem.x = 0.5f * mem.x + a[u].x - spk.x;
            mem.y = 0.5f * mem.y + a[u].y - spk.y;
            mem.z = 0.5f * mem.z + a[u].z - spk.z;
            mem.w = 0.5f * mem.w + a[u].w - spk.w;

            spk.x = (mem.x > 1.0f) ? 1.0f : 0.0f;
            spk.y = (mem.y > 1.0f) ? 1.0f : 0.0f;
            spk.z = (mem.z > 1.0f) ? 1.0f : 0.0f;
            spk.w = (mem.w > 1.0f) ? 1.0f : 0.0f;

            __stcs(op + (size_t)(t + u) * BN4, spk);
        }
    }
}

extern "C" void kernel_launch(void* const* d_in, const int* in_sizes, int n_in,
                              void* d_out, int out_size)
{
    const float4* x4 = (const float4*)d_in[0];
    float4* o4 = (float4*)d_out;
    snn_leaky_kernel<<<BN4 / BLOCK, BLOCK>>>(x4, o4);
}